// round 8
// baseline (speedup 1.0000x reference)
#include <cuda_runtime.h>
#include <cstdint>

// ---------------------------------------------------------------------------
// Warp-collective Gumbel top-k selection for a single rank my_k.
// 64 logits; each lane owns entries {lane, lane+32}. Runs in warp 0 only.
// Writes (index, weight) for rank my_k into smem. Optionally writes the
// masked logit vector to out_logit (one designated block only).
// ---------------------------------------------------------------------------
__device__ __forceinline__ void warp_select(const float* __restrict__ logit,
                                            const float* __restrict__ bg,
                                            const float* __restrict__ gumbel,
                                            int my_k,
                                            int* s_idx, float* s_w,
                                            float* out_logit) {
    const int lane = threadIdx.x & 31;

    float ml0 = logit[lane]      + logf(fmaxf(1.0f - bg[lane],      1e-8f));
    float ml1 = logit[lane + 32] + logf(fmaxf(1.0f - bg[lane + 32], 1e-8f));
    if (out_logit) {
        out_logit[lane]      = ml0;
        out_logit[lane + 32] = ml1;
    }

    float p0 = ml0 + gumbel[lane];
    float p1 = ml1 + gumbel[lane + 32];
    float m0 = 0.0f, m1 = 0.0f;

    for (int it = 0; it <= my_k; ++it) {
        float v0 = p0 + m0;
        float v1 = p1 + m1;
        // local argmax, tie -> lower index
        float best = v0;
        int bi = lane;
        if (v1 > best) { best = v1; bi = lane + 32; }
        // warp argmax reduction, tie -> lower index
        #pragma unroll
        for (int off = 16; off > 0; off >>= 1) {
            float ob = __shfl_xor_sync(0xffffffffu, best, off);
            int   oi = __shfl_xor_sync(0xffffffffu, bi,   off);
            if (ob > best || (ob == best && oi < bi)) { best = ob; bi = oi; }
        }
        if (it == my_k) {
            // softmax value at argmax: 1 / sum_j exp((v_j - best)/tau), tau=0.01
            float s = expf((v0 - best) * 100.0f) + expf((v1 - best) * 100.0f);
            #pragma unroll
            for (int off = 16; off > 0; off >>= 1)
                s += __shfl_xor_sync(0xffffffffu, s, off);
            if (lane == 0) { *s_idx = bi; *s_w = 1.0f / s; }
        } else {
            // mask out the selected entry for the next iteration
            if (bi == lane)      m0 = -1e9f;
            if (bi == lane + 32) m1 = -1e9f;
        }
    }
}

// ---------------------------------------------------------------------------
// Fused gather: one grid covers image (scaled by w_k) and label (unscaled).
//   blocks [0, kk*1024)            : image  — 1024 blocks per k
//   blocks [kk*1024, kk*1024+kk*256): label — 256 blocks per k
// One float4 per thread; patch row = 16 contiguous float4 -> fully coalesced.
// The very first label block also writes the masked_logit output tail.
// ---------------------------------------------------------------------------
__global__ void __launch_bounds__(256)
gather_kernel(const float* __restrict__ img,
              const float* __restrict__ lab,
              const float* __restrict__ logit,
              const float* __restrict__ bg,
              const float* __restrict__ gumbel,
              float* __restrict__ out_img,
              float* __restrict__ out_lab,
              float* __restrict__ out_logit,
              int img_blocks) {               // kk * 1024
    __shared__ int   s_idx;
    __shared__ float s_w;

    const bool is_img = (int)blockIdx.x < img_blocks;
    const int  lb     = is_img ? (int)blockIdx.x : (int)blockIdx.x - img_blocks;
    const int  my_k   = is_img ? (lb >> 10) : (lb >> 8);

    if (threadIdx.x < 32)
        warp_select(logit, bg, gumbel, my_k, &s_idx, &s_w,
                    (!is_img && lb == 0) ? out_logit : nullptr);
    __syncthreads();

    const int n  = s_idx;
    const int hn = n >> 4, wn = (n >> 2) & 3, dn = n & 3;

    if (is_img) {
        const unsigned i = (unsigned)lb * 256u + threadIdx.x;  // < 2^21
        int r   = i & ((4 << 16) - 1);                 // offset within this k
        int c   = r >> 16;
        int off = r & 65535;
        int dp4 = off & 15, wp = (off >> 4) & 63, hp = off >> 10;
        long src = (long)c * 16777216
                 + (long)(hn * 64 + hp) * 65536
                 + (long)(wn * 64 + wp) * 256
                 + (long)(dn * 64 + dp4 * 4);
        float4 v = *(const float4*)(img + src);
        float w = s_w;
        v.x *= w; v.y *= w; v.z *= w; v.w *= w;
        ((float4*)out_img)[i] = v;
    } else {
        const unsigned j = (unsigned)lb * 256u + threadIdx.x;  // < 2^19
        int off = j & 65535;
        int dp4 = off & 15, wp = (off >> 4) & 63, hp = off >> 10;
        long src = (long)(hn * 64 + hp) * 65536
                 + (long)(wn * 64 + wp) * 256
                 + (long)(dn * 64 + dp4 * 4);
        ((float4*)out_lab)[j] = *(const float4*)(lab + src);
    }
}

extern "C" void kernel_launch(void* const* d_in, const int* in_sizes, int n_in,
                              void* d_out, int out_size) {
    const float* image  = (const float*)d_in[0];   // [1,4,256,256,256]
    const float* label  = (const float*)d_in[1];   // [1,1,256,256,256]
    const float* logit  = (const float*)d_in[2];   // [1,1,4,4,4]
    const float* bg     = (const float*)d_in[3];   // [1,1,4,4,4]
    const float* gumbel = (const float*)d_in[4];   // [1,64]

    // k derived from the output size: out = k*(4+1)*64^3 + 64 floats
    int kk = (int)(((long)out_size - 64) / (5L * 262144));
    if (kk < 1 || kk > 64) kk = 8;

    float* out       = (float*)d_out;
    float* out_lab   = out + (long)kk * 4 * 262144;        // after img block
    float* out_logit = out_lab + (long)kk * 262144;        // after lab block

    const int img_blocks = kk * 1024;
    const int lab_blocks = kk * 256;
    gather_kernel<<<img_blocks + lab_blocks, 256>>>(
        image, label, logit, bg, gumbel, out, out_lab, out_logit, img_blocks);
}